// round 8
// baseline (speedup 1.0000x reference)
#include <cuda_runtime.h>
#include <cuda_fp16.h>
#include <mma.h>
#include <cstddef>

using namespace nvcuda;

#define L_NODES 100000
#define NFEAT   256
#define JDIM    128
#define SSAMP   8
#define MTILE   64
#define NTHREADS 256

// ---------------- scratch (static __device__ — no allocations allowed) -----
__device__ __half g_ABh[(size_t)L_NODES * 2 * JDIM];  // 51.2 MB  [A|B] fp16
__device__ __half g_W1h[NFEAT * JDIM];                // Wh1 fp16 (256x128)
__device__ __half g_Wgh[2 * JDIM * JDIM];             // Wg1 fp16 (256x128)

// ---------------- smem geometry --------------------------------------------
#define XS_LD 264     // 256 + 8 pad halves
#define HS_LD 136     // 128 + 8 pad halves
#define CS_LD 132     // floats

#define XS_BYTES (MTILE * XS_LD * 2)     // 33792
#define H_OFF    XS_BYTES                // Hh lives after Xs
#define H_BYTES  (MTILE * HS_LD * 2)     // 17408
#define SMEM_F12 (XS_BYTES + H_BYTES)    // 51200  (Cs[33792] unions Xs)
#define SMEM_FIN 33792                   // max(Eh 17408, Cs 33792) union

extern __shared__ char smem_raw[];

__device__ __forceinline__ void sts_half4(__half* dst, float4 v)
{
    __half2 h[2];
    h[0] = __floats2half2_rn(v.x, v.y);
    h[1] = __floats2half2_rn(v.z, v.w);
    *(uint2*)dst = *(uint2*)h;
}

// mma 32x32 warp tile, one K=32 chunk; A from smem, B from GLOBAL (ldm=128)
__device__ __forceinline__ void mma_chunk_gB(
    const __half* As, int ldA, const __half* Bg,
    wmma::fragment<wmma::accumulator, 16, 16, 16, float> (&c)[2][2],
    int wRow, int wCol)
{
#pragma unroll
    for (int ks = 0; ks < 2; ++ks) {
        wmma::fragment<wmma::matrix_a, 16, 16, 16, __half, wmma::row_major> a[2];
        wmma::fragment<wmma::matrix_b, 16, 16, 16, __half, wmma::row_major> b[2];
#pragma unroll
        for (int mi = 0; mi < 2; ++mi)
            wmma::load_matrix_sync(a[mi], &As[(wRow * 32 + mi * 16) * ldA + ks * 16], ldA);
#pragma unroll
        for (int ni = 0; ni < 2; ++ni)
            wmma::load_matrix_sync(b[ni], &Bg[(size_t)(ks * 16) * JDIM + wCol * 32 + ni * 16], JDIM);
#pragma unroll
        for (int mi = 0; mi < 2; ++mi)
#pragma unroll
            for (int ni = 0; ni < 2; ++ni)
                wmma::mma_sync(c[mi][ni], a[mi], b[ni], c[mi][ni]);
    }
}

// ---------------- weight fp32 -> fp16 prepass ------------------------------
__global__ void convert_w(const float* __restrict__ Wh1, const float* __restrict__ Wg1)
{
    const int i = blockIdx.x * 256 + threadIdx.x;   // 0..32767
    g_W1h[i] = __float2half(Wh1[i]);
    g_Wgh[i] = __float2half(Wg1[i]);
}

// ---------------- fused12: ABh = fp16( relu(X@Wh1+b) @ [Wtop|Wbot] ) -------
__global__ __launch_bounds__(NTHREADS, 2) void fused12(
    const float* __restrict__ X, const float* __restrict__ bh1,
    __half* __restrict__ ABh, int M)
{
    char* sm = smem_raw;
    __half* Xs = (__half*)sm;
    __half* Hh = (__half*)(sm + H_OFF);
    float*  Cs = (float*)sm;             // union with Xs (after phase A mma)

    const int tid  = threadIdx.x;
    const int wId  = tid >> 5;
    const int wRow = wId >> 2;           // 0..1
    const int wCol = wId & 3;            // 0..3
    const int rowN = blockIdx.x * MTILE;

    // ---- stage full X tile 64x256 fp32 -> fp16 (one pass, one sync) ----
#pragma unroll
    for (int it = 0; it < 16; ++it) {
        const int i  = tid + it * NTHREADS;   // 0..4095 float4 slots
        const int r  = i >> 6;
        const int c4 = (i & 63) * 4;
        const int gr = rowN + r;
        float4 v = (gr < M) ? *(const float4*)&X[(size_t)gr * NFEAT + c4]
                            : make_float4(0.f, 0.f, 0.f, 0.f);
        sts_half4(&Xs[r * XS_LD + c4], v);
    }
    __syncthreads();

    // ---- phase A: acc = Xs @ W1h(global), 8 chunks, no inner syncs ----
    wmma::fragment<wmma::accumulator, 16, 16, 16, float> c[2][2];
#pragma unroll
    for (int mi = 0; mi < 2; ++mi)
#pragma unroll
        for (int ni = 0; ni < 2; ++ni) wmma::fill_fragment(c[mi][ni], 0.f);
#pragma unroll
    for (int kc = 0; kc < 8; ++kc)
        mma_chunk_gB(&Xs[kc * 32], XS_LD, &g_W1h[(size_t)(kc * 32) * JDIM], c, wRow, wCol);
    __syncthreads();   // Xs reads done -> Cs may overwrite

    // stage acc -> Cs -> bias+relu -> Hh(fp16)
#pragma unroll
    for (int mi = 0; mi < 2; ++mi)
#pragma unroll
        for (int ni = 0; ni < 2; ++ni)
            wmma::store_matrix_sync(&Cs[(wRow * 32 + mi * 16) * CS_LD + wCol * 32 + ni * 16],
                                    c[mi][ni], CS_LD, wmma::mem_row_major);
    __syncthreads();
#pragma unroll
    for (int it = 0; it < 8; ++it) {
        const int i  = tid + it * NTHREADS;
        const int r  = i >> 5;
        const int c4 = (i & 31) * 4;
        float4 v = *(float4*)&Cs[r * CS_LD + c4];
        v.x = fmaxf(v.x + bh1[c4 + 0], 0.f);
        v.y = fmaxf(v.y + bh1[c4 + 1], 0.f);
        v.z = fmaxf(v.z + bh1[c4 + 2], 0.f);
        v.w = fmaxf(v.w + bh1[c4 + 3], 0.f);
        sts_half4(&Hh[r * HS_LD + c4], v);
    }
    __syncthreads();

    // ---- phase B: AB[:, h*128:+128] = Hh @ Wg1h[h*128:+128, :] (B global) --
#pragma unroll
    for (int h = 0; h < 2; ++h) {
#pragma unroll
        for (int mi = 0; mi < 2; ++mi)
#pragma unroll
            for (int ni = 0; ni < 2; ++ni) wmma::fill_fragment(c[mi][ni], 0.f);
#pragma unroll
        for (int kc = 0; kc < 4; ++kc)
            mma_chunk_gB(&Hh[kc * 32], HS_LD,
                         &g_Wgh[(size_t)(h * 128 + kc * 32) * JDIM], c, wRow, wCol);
        __syncthreads();   // prior Cs reads (it=h-1 epilogue) done

#pragma unroll
        for (int mi = 0; mi < 2; ++mi)
#pragma unroll
            for (int ni = 0; ni < 2; ++ni)
                wmma::store_matrix_sync(&Cs[(wRow * 32 + mi * 16) * CS_LD + wCol * 32 + ni * 16],
                                        c[mi][ni], CS_LD, wmma::mem_row_major);
        __syncthreads();
#pragma unroll
        for (int it = 0; it < 8; ++it) {
            const int i  = tid + it * NTHREADS;
            const int r  = i >> 5;
            const int c4 = (i & 31) * 4;
            const int g2 = rowN + r;
            if (g2 < M)
                sts_half4(&ABh[(size_t)g2 * 256 + h * 128 + c4], *(float4*)&Cs[r * CS_LD + c4]);
        }
        __syncthreads();
    }
}

// ---------------- final: gather -> E(smem) -> E@Wbot -> Wf epilogue --------
__global__ __launch_bounds__(NTHREADS, 3) void final_fused(
    const int* __restrict__ idx0, const int* __restrict__ idx1,
    const float* __restrict__ bg, const float* __restrict__ Wf,
    const float* __restrict__ bf, const __half* __restrict__ ABh,
    float* __restrict__ out, int M)
{
    char* sm = smem_raw;
    __half* Eh = (__half*)sm;
    float*  Cs = (float*)sm;             // union (after mma reads of Eh)

    const int tid  = threadIdx.x;
    const int wId  = tid >> 5;
    const int lane = tid & 31;
    const int wRow = wId >> 2;
    const int wCol = wId & 3;
    const int rowN = blockIdx.x * MTILE;

    // gather: warp w computes rows w*8 .. w*8+7 of the E tile
    {
        const int c  = lane * 4;
        const float b0 = bg[c], b1 = bg[c + 1], b2 = bg[c + 2], b3 = bg[c + 3];
#pragma unroll
        for (int rr0 = 0; rr0 < 8; ++rr0) {
            const int rr = wId * 8 + rr0;
            const int g2 = rowN + rr;
            float4 e = make_float4(0.f, 0.f, 0.f, 0.f);
            if (g2 < M) {
                float4 acc = make_float4(0.f, 0.f, 0.f, 0.f);
#pragma unroll
                for (int s = 0; s < SSAMP; ++s) {
                    const int i0 = idx0[s * L_NODES + g2];
                    const int i1 = idx1[s * L_NODES + g2];
                    const uint2 au = *(const uint2*)&ABh[(size_t)i0 * 256 + c];
                    const uint2 bu = *(const uint2*)&ABh[(size_t)i1 * 256 + 128 + c];
                    const float2 a01 = __half22float2(*(const __half2*)&au.x);
                    const float2 a23 = __half22float2(*(const __half2*)&au.y);
                    const float2 b01 = __half22float2(*(const __half2*)&bu.x);
                    const float2 b23 = __half22float2(*(const __half2*)&bu.y);
                    acc.x += fmaxf(a01.x + b01.x + b0, 0.f);
                    acc.y += fmaxf(a01.y + b01.y + b1, 0.f);
                    acc.z += fmaxf(a23.x + b23.x + b2, 0.f);
                    acc.w += fmaxf(a23.y + b23.y + b3, 0.f);
                }
                const float inv = 1.f / (float)SSAMP;
                e.x = fmaxf(acc.x * inv, 0.f);
                e.y = fmaxf(acc.y * inv, 0.f);
                e.z = fmaxf(acc.z * inv, 0.f);
                e.w = fmaxf(acc.w * inv, 0.f);
            }
            sts_half4(&Eh[rr * HS_LD + c], e);
        }
    }
    __syncthreads();

    // GEMM: C = Eh(64x128) @ Wbot(global rows 128..255)
    wmma::fragment<wmma::accumulator, 16, 16, 16, float> c[2][2];
#pragma unroll
    for (int mi = 0; mi < 2; ++mi)
#pragma unroll
        for (int ni = 0; ni < 2; ++ni) wmma::fill_fragment(c[mi][ni], 0.f);
#pragma unroll
    for (int kc = 0; kc < 4; ++kc)
        mma_chunk_gB(&Eh[kc * 32], HS_LD,
                     &g_Wgh[(size_t)(128 + kc * 32) * JDIM], c, wRow, wCol);
    __syncthreads();   // Eh reads done -> Cs may overwrite

#pragma unroll
    for (int mi = 0; mi < 2; ++mi)
#pragma unroll
        for (int ni = 0; ni < 2; ++ni)
            wmma::store_matrix_sync(&Cs[(wRow * 32 + mi * 16) * CS_LD + wCol * 32 + ni * 16],
                                    c[mi][ni], CS_LD, wmma::mem_row_major);
    __syncthreads();

    // epilogue: 4 threads/row, each covers 32 features
    const int r  = tid >> 2;
    const int q  = tid & 3;
    const int f0 = q * 32;
    const int g2 = rowN + r;
    float s0 = 0.f, s1 = 0.f;
    if (g2 < M) {
#pragma unroll
        for (int j = 0; j < 8; ++j) {
            const int f = f0 + j * 4;
            const float4 cv = *(float4*)&Cs[r * CS_LD + f];
            const uint2 au = *(const uint2*)&ABh[(size_t)g2 * 256 + f];  // A = H@Wtop
            const float2 a01 = __half22float2(*(const __half2*)&au.x);
            const float2 a23 = __half22float2(*(const __half2*)&au.y);
            const float e0 = fmaxf(a01.x + cv.x + bg[f + 0], 0.f);
            const float e1 = fmaxf(a01.y + cv.y + bg[f + 1], 0.f);
            const float e2 = fmaxf(a23.x + cv.z + bg[f + 2], 0.f);
            const float e3 = fmaxf(a23.y + cv.w + bg[f + 3], 0.f);
            s0 += e0 * Wf[(f + 0) * 2] + e1 * Wf[(f + 1) * 2]
                + e2 * Wf[(f + 2) * 2] + e3 * Wf[(f + 3) * 2];
            s1 += e0 * Wf[(f + 0) * 2 + 1] + e1 * Wf[(f + 1) * 2 + 1]
                + e2 * Wf[(f + 2) * 2 + 1] + e3 * Wf[(f + 3) * 2 + 1];
        }
    }
#pragma unroll
    for (int off = 1; off <= 2; off <<= 1) {
        s0 += __shfl_xor_sync(0xffffffffu, s0, off);
        s1 += __shfl_xor_sync(0xffffffffu, s1, off);
    }
    if (q == 0 && g2 < M) {
        out[(size_t)g2 * 2 + 0] = s0 + bf[0];
        out[(size_t)g2 * 2 + 1] = s1 + bf[1];
    }
}

// ---------------------------------------------------------------------------
extern "C" void kernel_launch(void* const* d_in, const int* in_sizes, int n_in,
                              void* d_out, int out_size)
{
    const float* X    = (const float*)d_in[0];
    const float* Wh1  = (const float*)d_in[1];
    const float* bh1  = (const float*)d_in[2];
    const float* Wg1  = (const float*)d_in[3];
    const float* bg1  = (const float*)d_in[4];
    const float* Wf   = (const float*)d_in[5];
    const float* bf   = (const float*)d_in[6];
    const int*   idx0 = (const int*)d_in[7];
    const int*   idx1 = (const int*)d_in[8];
    float* out = (float*)d_out;

    __half* ABh;
    cudaGetSymbolAddress((void**)&ABh, g_ABh);

    cudaFuncSetAttribute(fused12, cudaFuncAttributeMaxDynamicSharedMemorySize, SMEM_F12);
    cudaFuncSetAttribute(final_fused, cudaFuncAttributeMaxDynamicSharedMemorySize, SMEM_FIN);

    const int mtiles = (L_NODES + MTILE - 1) / MTILE;   // 1563

    convert_w<<<128, 256>>>(Wh1, Wg1);

    // 1+2) ABh = fp16( relu(X@Wh1+bh1) @ [Wtop|Wbot] )
    fused12<<<mtiles, NTHREADS, SMEM_F12>>>(X, bh1, ABh, L_NODES);

    // 3+4+5) gather -> E tile -> E@Wbot -> Wf epilogue
    final_fused<<<mtiles, NTHREADS, SMEM_FIN>>>(
        idx0, idx1, bg1, Wf, bf, ABh, out, L_NODES);
}

// round 10
// speedup vs baseline: 1.5429x; 1.5429x over previous
#include <cuda_runtime.h>
#include <cuda_fp16.h>
#include <mma.h>
#include <cstddef>

using namespace nvcuda;

#define L_NODES 100000
#define NFEAT   256
#define JDIM    128
#define SSAMP   8
#define MTILE   64
#define NTHREADS 256

// ---------------- scratch (static __device__ — no allocations allowed) -----
__device__ __half g_ABh[(size_t)L_NODES * 2 * JDIM];  // 51.2 MB  [A|B] fp16
__device__ __half g_W1h[NFEAT * JDIM];                // Wh1 fp16 (256x128)
__device__ __half g_Wgh[2 * JDIM * JDIM];             // Wg1 fp16 (256x128)

// ---------------- smem geometry (halves unless noted) ----------------------
#define AS_LD 40      // 32 + 8 pad halves
#define BS_LD 136     // 128 + 8 pad halves
#define HS_LD 136
#define WP_LD 136
#define CS_LD 132     // floats

#define H_BYTES   (MTILE * HS_LD * 2)          // 17408
#define SCR_OFF   H_BYTES
#define AS_BYTES  (MTILE * AS_LD * 2)          // 5120
#define BS_BYTES  (32 * BS_LD * 2)             // 8704
#define WP_BYTES  (128 * WP_LD * 2)            // 34816
#define CS_BYTES  (MTILE * CS_LD * 4)          // 33792
#define SMEM_TOTAL (SCR_OFF + WP_BYTES)        // 52224  (union: scratch|Wp|Cs)

extern __shared__ char smem_raw[];

// ---------------- fp16 mma core: warp tile 32x32 (A,B in smem) -------------
__device__ __forceinline__ void mma_chunk32(
    const __half* As, const __half* Bs, int ldA, int ldB,
    wmma::fragment<wmma::accumulator, 16, 16, 16, float> (&c)[2][2],
    int wRow, int wCol)
{
#pragma unroll
    for (int ks = 0; ks < 2; ++ks) {
        wmma::fragment<wmma::matrix_a, 16, 16, 16, __half, wmma::row_major> a[2];
        wmma::fragment<wmma::matrix_b, 16, 16, 16, __half, wmma::row_major> b[2];
#pragma unroll
        for (int mi = 0; mi < 2; ++mi)
            wmma::load_matrix_sync(a[mi], &As[(wRow * 32 + mi * 16) * ldA + ks * 16], ldA);
#pragma unroll
        for (int ni = 0; ni < 2; ++ni)
            wmma::load_matrix_sync(b[ni], &Bs[(ks * 16) * ldB + wCol * 32 + ni * 16], ldB);
#pragma unroll
        for (int mi = 0; mi < 2; ++mi)
#pragma unroll
            for (int ni = 0; ni < 2; ++ni)
                wmma::mma_sync(c[mi][ni], a[mi], b[ni], c[mi][ni]);
    }
}

__device__ __forceinline__ void sts_half4(__half* dst, float4 v)
{
    __half2 h[2];
    h[0] = __floats2half2_rn(v.x, v.y);
    h[1] = __floats2half2_rn(v.z, v.w);
    *(uint2*)dst = *(uint2*)h;
}

// ---------------- weight fp32 -> fp16 prepass ------------------------------
__global__ void convert_w(const float* __restrict__ Wh1, const float* __restrict__ Wg1)
{
    const int i = blockIdx.x * 256 + threadIdx.x;   // 0..32767
    g_W1h[i] = __float2half(Wh1[i]);
    g_Wgh[i] = __float2half(Wg1[i]);
}

// ---------------- fused12: ABh = fp16( relu(X@Wh1+b) @ [Wtop|Wbot] ) -------
__global__ __launch_bounds__(NTHREADS, 2) void fused12(
    const float* __restrict__ X, const float* __restrict__ bh1,
    __half* __restrict__ ABh, int M)
{
    char* sm = smem_raw;
    __half* Hh  = (__half*)sm;
    char*   scr = sm + SCR_OFF;
    __half* AsB[2] = { (__half*)scr, (__half*)(scr + AS_BYTES) };
    __half* BsB[2] = { (__half*)(scr + 2 * AS_BYTES),
                       (__half*)(scr + 2 * AS_BYTES + BS_BYTES) };
    float*  Cs = (float*)scr;
    __half* Wp = (__half*)scr;

    const int tid  = threadIdx.x;
    const int wId  = tid >> 5;
    const int wRow = wId >> 2;           // 0..1
    const int wCol = wId & 3;            // 0..3
    const int rowN = blockIdx.x * MTILE;

    const int aR  = tid >> 2;            // 0..63
    const int aC  = (tid & 3) * 4;       // +16 on it=1
    const int bR  = tid >> 4;            // 0..15 ; +16 on it=1
    const int bc8 = (tid & 15) * 8;      // halves

    wmma::fragment<wmma::accumulator, 16, 16, 16, float> c[2][2];
#pragma unroll
    for (int mi = 0; mi < 2; ++mi)
#pragma unroll
        for (int ni = 0; ni < 2; ++ni) wmma::fill_fragment(c[mi][ni], 0.f);

    // ---- phase A: acc = X[rowN:+64] @ Wh1 (K=256, 8 chunks of 32) ----
    const int gr = rowN + aR;
    float4 aReg[2];
    uint4  bReg[2];
#pragma unroll
    for (int it = 0; it < 2; ++it) {
        aReg[it] = (gr < M) ? *(const float4*)&X[(size_t)gr * NFEAT + aC + it * 16]
                            : make_float4(0.f, 0.f, 0.f, 0.f);
        bReg[it] = *(const uint4*)&g_W1h[(bR + it * 16) * JDIM + bc8];
    }
#pragma unroll
    for (int kt = 0; kt < 8; ++kt) {
        __half* As = AsB[kt & 1];
        __half* Bs = BsB[kt & 1];
#pragma unroll
        for (int it = 0; it < 2; ++it) {
            sts_half4(&As[aR * AS_LD + aC + it * 16], aReg[it]);
            *(uint4*)&Bs[(bR + it * 16) * BS_LD + bc8] = bReg[it];
        }
        __syncthreads();
        if (kt < 7) {
            const int ko = (kt + 1) * 32;
#pragma unroll
            for (int it = 0; it < 2; ++it) {
                aReg[it] = (gr < M) ? *(const float4*)&X[(size_t)gr * NFEAT + ko + aC + it * 16]
                                    : make_float4(0.f, 0.f, 0.f, 0.f);
                bReg[it] = *(const uint4*)&g_W1h[(ko + bR + it * 16) * JDIM + bc8];
            }
        }
        mma_chunk32(As, Bs, AS_LD, BS_LD, c, wRow, wCol);
        __syncthreads();
    }

    // stage acc -> Cs -> bias+relu -> Hh(fp16)
#pragma unroll
    for (int mi = 0; mi < 2; ++mi)
#pragma unroll
        for (int ni = 0; ni < 2; ++ni)
            wmma::store_matrix_sync(&Cs[(wRow * 32 + mi * 16) * CS_LD + wCol * 32 + ni * 16],
                                    c[mi][ni], CS_LD, wmma::mem_row_major);
    __syncthreads();
#pragma unroll
    for (int it = 0; it < 8; ++it) {
        const int i  = tid + it * NTHREADS;
        const int r  = i >> 5;
        const int c4 = (i & 31) * 4;
        float4 v = *(float4*)&Cs[r * CS_LD + c4];
        v.x = fmaxf(v.x + bh1[c4 + 0], 0.f);
        v.y = fmaxf(v.y + bh1[c4 + 1], 0.f);
        v.z = fmaxf(v.z + bh1[c4 + 2], 0.f);
        v.w = fmaxf(v.w + bh1[c4 + 3], 0.f);
        sts_half4(&Hh[r * HS_LD + c4], v);
    }
    __syncthreads();

    // ---- phase B: AB[:, h*128:+128] = H @ Wg1[h*128:+128, :] ----
#pragma unroll
    for (int h = 0; h < 2; ++h) {
        // weight panel 128x128 fp16 -> smem (uint4 copy, 8/thread)
#pragma unroll
        for (int it = 0; it < 8; ++it) {
            const int i  = tid + it * NTHREADS;
            const int k  = i >> 4;
            const int c8 = (i & 15) * 8;
            *(uint4*)&Wp[k * WP_LD + c8] = *(const uint4*)&g_Wgh[(size_t)(h * 128 + k) * JDIM + c8];
        }
        __syncthreads();

#pragma unroll
        for (int mi = 0; mi < 2; ++mi)
#pragma unroll
            for (int ni = 0; ni < 2; ++ni) wmma::fill_fragment(c[mi][ni], 0.f);
#pragma unroll
        for (int kc = 0; kc < 4; ++kc)
            mma_chunk32(&Hh[kc * 32], &Wp[(kc * 32) * WP_LD], HS_LD, WP_LD, c, wRow, wCol);
        __syncthreads();  // Wp reads done -> Cs may overwrite

#pragma unroll
        for (int mi = 0; mi < 2; ++mi)
#pragma unroll
            for (int ni = 0; ni < 2; ++ni)
                wmma::store_matrix_sync(&Cs[(wRow * 32 + mi * 16) * CS_LD + wCol * 32 + ni * 16],
                                        c[mi][ni], CS_LD, wmma::mem_row_major);
        __syncthreads();
#pragma unroll
        for (int it = 0; it < 8; ++it) {
            const int i  = tid + it * NTHREADS;
            const int r  = i >> 5;
            const int c4 = (i & 31) * 4;
            const int g2 = rowN + r;
            if (g2 < M)
                sts_half4(&ABh[(size_t)g2 * 256 + h * 128 + c4], *(float4*)&Cs[r * CS_LD + c4]);
        }
        __syncthreads();  // Cs free before next h
    }
}

// ---------------- final: gather -> E tile(smem) -> GEMM -> Wf epilogue -----
__global__ __launch_bounds__(NTHREADS, 3) void final_fused(
    const int* __restrict__ idx0, const int* __restrict__ idx1,
    const float* __restrict__ bg, const float* __restrict__ Wf,
    const float* __restrict__ bf, const __half* __restrict__ ABh,
    float* __restrict__ out, int M)
{
    char* sm = smem_raw;
    __half* Eh = (__half*)sm;
    __half* Wp = (__half*)(sm + SCR_OFF);
    float*  Cs = (float*)(sm + SCR_OFF);

    const int tid  = threadIdx.x;
    const int wId  = tid >> 5;
    const int lane = tid & 31;
    const int wRow = wId >> 2;
    const int wCol = wId & 3;
    const int rowN = blockIdx.x * MTILE;

    // load Wbot panel (Wg1 rows 128..255) fp16 -> smem
#pragma unroll
    for (int it = 0; it < 8; ++it) {
        const int i  = tid + it * NTHREADS;
        const int k  = i >> 4;
        const int c8 = (i & 15) * 8;
        *(uint4*)&Wp[k * WP_LD + c8] = *(const uint4*)&g_Wgh[(size_t)(128 + k) * JDIM + c8];
    }

    // gather: warp w computes rows w*8 .. w*8+7 of the E tile
    {
        const int c  = lane * 4;
        const float b0 = bg[c], b1 = bg[c + 1], b2 = bg[c + 2], b3 = bg[c + 3];
#pragma unroll
        for (int rr0 = 0; rr0 < 8; ++rr0) {
            const int rr = wId * 8 + rr0;
            const int g2 = rowN + rr;
            float4 e = make_float4(0.f, 0.f, 0.f, 0.f);
            if (g2 < M) {
                float4 acc = make_float4(0.f, 0.f, 0.f, 0.f);
#pragma unroll
                for (int s = 0; s < SSAMP; ++s) {
                    const int i0 = idx0[s * L_NODES + g2];
                    const int i1 = idx1[s * L_NODES + g2];
                    const uint2 au = *(const uint2*)&ABh[(size_t)i0 * 256 + c];
                    const uint2 bu = *(const uint2*)&ABh[(size_t)i1 * 256 + 128 + c];
                    const float2 a01 = __half22float2(*(const __half2*)&au.x);
                    const float2 a23 = __half22float2(*(const __half2*)&au.y);
                    const float2 b01 = __half22float2(*(const __half2*)&bu.x);
                    const float2 b23 = __half22float2(*(const __half2*)&bu.y);
                    acc.x += fmaxf(a01.x + b01.x + b0, 0.f);
                    acc.y += fmaxf(a01.y + b01.y + b1, 0.f);
                    acc.z += fmaxf(a23.x + b23.x + b2, 0.f);
                    acc.w += fmaxf(a23.y + b23.y + b3, 0.f);
                }
                const float inv = 1.f / (float)SSAMP;
                e.x = fmaxf(acc.x * inv, 0.f);
                e.y = fmaxf(acc.y * inv, 0.f);
                e.z = fmaxf(acc.z * inv, 0.f);
                e.w = fmaxf(acc.w * inv, 0.f);
            }
            sts_half4(&Eh[rr * HS_LD + c], e);
        }
    }
    __syncthreads();

    // GEMM: C = E(64x128) @ Wbot(128x128), operands in smem
    wmma::fragment<wmma::accumulator, 16, 16, 16, float> c[2][2];
#pragma unroll
    for (int mi = 0; mi < 2; ++mi)
#pragma unroll
        for (int ni = 0; ni < 2; ++ni) wmma::fill_fragment(c[mi][ni], 0.f);
#pragma unroll
    for (int kc = 0; kc < 4; ++kc)
        mma_chunk32(&Eh[kc * 32], &Wp[(kc * 32) * WP_LD], HS_LD, WP_LD, c, wRow, wCol);
    __syncthreads();  // Wp reads done -> Cs may overwrite

#pragma unroll
    for (int mi = 0; mi < 2; ++mi)
#pragma unroll
        for (int ni = 0; ni < 2; ++ni)
            wmma::store_matrix_sync(&Cs[(wRow * 32 + mi * 16) * CS_LD + wCol * 32 + ni * 16],
                                    c[mi][ni], CS_LD, wmma::mem_row_major);
    __syncthreads();

    // epilogue: 4 threads/row (64 rows), each covers 32 features
    const int r  = tid >> 2;
    const int q  = tid & 3;
    const int f0 = q * 32;
    const int g2 = rowN + r;
    float s0 = 0.f, s1 = 0.f;
    if (g2 < M) {
#pragma unroll
        for (int j = 0; j < 8; ++j) {
            const int f = f0 + j * 4;
            const float4 cv = *(float4*)&Cs[r * CS_LD + f];
            const uint2 au = *(const uint2*)&ABh[(size_t)g2 * 256 + f];  // A = H@Wtop
            const float2 a01 = __half22float2(*(const __half2*)&au.x);
            const float2 a23 = __half22float2(*(const __half2*)&au.y);
            const float e0 = fmaxf(a01.x + cv.x + bg[f + 0], 0.f);
            const float e1 = fmaxf(a01.y + cv.y + bg[f + 1], 0.f);
            const float e2 = fmaxf(a23.x + cv.z + bg[f + 2], 0.f);
            const float e3 = fmaxf(a23.y + cv.w + bg[f + 3], 0.f);
            s0 += e0 * Wf[(f + 0) * 2] + e1 * Wf[(f + 1) * 2]
                + e2 * Wf[(f + 2) * 2] + e3 * Wf[(f + 3) * 2];
            s1 += e0 * Wf[(f + 0) * 2 + 1] + e1 * Wf[(f + 1) * 2 + 1]
                + e2 * Wf[(f + 2) * 2 + 1] + e3 * Wf[(f + 3) * 2 + 1];
        }
    }
#pragma unroll
    for (int off = 1; off <= 2; off <<= 1) {
        s0 += __shfl_xor_sync(0xffffffffu, s0, off);
        s1 += __shfl_xor_sync(0xffffffffu, s1, off);
    }
    if (q == 0 && g2 < M) {
        out[(size_t)g2 * 2 + 0] = s0 + bf[0];
        out[(size_t)g2 * 2 + 1] = s1 + bf[1];
    }
}

// ---------------------------------------------------------------------------
extern "C" void kernel_launch(void* const* d_in, const int* in_sizes, int n_in,
                              void* d_out, int out_size)
{
    const float* X    = (const float*)d_in[0];
    const float* Wh1  = (const float*)d_in[1];
    const float* bh1  = (const float*)d_in[2];
    const float* Wg1  = (const float*)d_in[3];
    const float* bg1  = (const float*)d_in[4];
    const float* Wf   = (const float*)d_in[5];
    const float* bf   = (const float*)d_in[6];
    const int*   idx0 = (const int*)d_in[7];
    const int*   idx1 = (const int*)d_in[8];
    float* out = (float*)d_out;

    __half* ABh;
    cudaGetSymbolAddress((void**)&ABh, g_ABh);

    cudaFuncSetAttribute(fused12, cudaFuncAttributeMaxDynamicSharedMemorySize, SMEM_TOTAL);
    cudaFuncSetAttribute(final_fused, cudaFuncAttributeMaxDynamicSharedMemorySize, SMEM_TOTAL);

    const int mtiles = (L_NODES + MTILE - 1) / MTILE;   // 1563

    // 0) weights -> fp16
    convert_w<<<128, 256>>>(Wh1, Wg1);

    // 1+2) ABh = fp16( relu(X@Wh1+bh1) @ [Wtop|Wbot] )
    fused12<<<mtiles, NTHREADS, SMEM_TOTAL>>>(X, bh1, ABh, L_NODES);

    // 3+4+5) gather -> E tile -> E@Wbot -> Wf epilogue
    final_fused<<<mtiles, NTHREADS, SMEM_TOTAL>>>(
        idx0, idx1, bg1, Wf, bf, ABh, out, L_NODES);
}